// round 3
// baseline (speedup 1.0000x reference)
#include <cuda_runtime.h>

#define NNODE 50000
#define NEDGE 800000
#define DIM   64
#define NREL  65
#define TILE  128
#define EPB   2048
#define NB    ((NEDGE + EPB - 1) / EPB)
#define NTILES_MAX ((NEDGE + TILE - 1) / TILE + NREL)
#define SA    68   // padded smem row stride (floats)

// ---- scratch (static device globals; no allocation) ----
__device__ int   g_cnt[NNODE * NREL];
__device__ int   g_blockHist[NB * NREL];
__device__ int   g_relCnt[NREL];
__device__ int   g_relOff[NREL + 1];
__device__ int   g_tileBase[NREL + 1];
__device__ int   g_tileRel[NTILES_MAX];
__device__ int   g_tileStart[NTILES_MAX];
__device__ int   g_numTiles;
__device__ int   g_srcP[NEDGE];
__device__ int   g_dstP[NEDGE];
__device__ float g_normP[NEDGE];
__device__ float g_h[NNODE * DIM];

__device__ __forceinline__ unsigned f2tf(float f) {
    unsigned u; asm("cvt.rna.tf32.f32 %0, %1;" : "=r"(u) : "f"(f)); return u;
}

#define MMA_TF32(c, a, b0, b1)                                                   \
    asm volatile("mma.sync.aligned.m16n8k8.row.col.f32.tf32.tf32.f32 "           \
                 "{%0,%1,%2,%3},{%4,%5,%6,%7},{%8,%9},{%0,%1,%2,%3};"            \
                 : "+f"(c[0]), "+f"(c[1]), "+f"(c[2]), "+f"(c[3])                \
                 : "r"(a[0]), "r"(a[1]), "r"(a[2]), "r"(a[3]), "r"(b0), "r"(b1))

// ---------------------------------------------------------------- zero g_cnt
__global__ void k_zero() {
    int i = blockIdx.x * blockDim.x + threadIdx.x;
    if (i < NNODE * NREL / 4) {
        int4 z = make_int4(0, 0, 0, 0);
        ((int4*)g_cnt)[i] = z;
    }
}

// ---------------------------------------------------------------- histogram
__global__ void __launch_bounds__(256) k_hist(const int* __restrict__ dst,
                                              const int* __restrict__ et) {
    __shared__ int h[NREL];
    int tid = threadIdx.x, b = blockIdx.x;
    if (tid < NREL) h[tid] = 0;
    __syncthreads();
    int s = b * EPB, e_end = min(s + EPB, NEDGE);
    for (int e = s + tid; e < e_end; e += 256) {
        int r = et[e];
        atomicAdd(&h[r], 1);
        atomicAdd(&g_cnt[dst[e] * NREL + r], 1);
    }
    __syncthreads();
    if (tid < NREL) g_blockHist[b * NREL + tid] = h[tid];
}

// ---------------------------------------------------------------- per-relation block scan
__global__ void k_scanRel() {
    __shared__ int v[NB];
    int r = blockIdx.x, tid = threadIdx.x;
    for (int b = tid; b < NB; b += blockDim.x) v[b] = g_blockHist[b * NREL + r];
    __syncthreads();
    if (tid == 0) {
        int acc = 0;
        for (int b = 0; b < NB; b++) { int t = v[b]; v[b] = acc; acc += t; }
        g_relCnt[r] = acc;
    }
    __syncthreads();
    for (int b = tid; b < NB; b += blockDim.x) g_blockHist[b * NREL + r] = v[b];
}

// ---------------------------------------------------------------- relation offsets
__global__ void k_scan() {
    if (threadIdx.x == 0) {
        int eo = 0, to = 0;
        for (int r = 0; r < NREL; r++) {
            g_relOff[r] = eo; g_tileBase[r] = to;
            int c = g_relCnt[r];
            eo += c;
            to += (c + TILE - 1) / TILE;
        }
        g_relOff[NREL] = eo;
        g_tileBase[NREL] = to;
        g_numTiles = to;
    }
}

// ---------------------------------------------------------------- parallel tile table
__global__ void k_tiles() {
    int t = blockIdx.x * blockDim.x + threadIdx.x;
    if (t >= g_numTiles) return;
    int lo = 0, hi = NREL;
    while (lo + 1 < hi) {
        int mid = (lo + hi) >> 1;
        if (g_tileBase[mid] <= t) lo = mid; else hi = mid;
    }
    g_tileRel[t]   = lo;
    g_tileStart[t] = g_relOff[lo] + (t - g_tileBase[lo]) * TILE;
}

// ---------------------------------------------------------------- scatter sorted arrays
__global__ void __launch_bounds__(256) k_scatter(const int* __restrict__ src,
                                                 const int* __restrict__ dst,
                                                 const int* __restrict__ et) {
    __shared__ int cur[NREL];
    int tid = threadIdx.x, b = blockIdx.x;
    if (tid < NREL) cur[tid] = g_relOff[tid] + g_blockHist[b * NREL + tid];
    __syncthreads();
    int s = b * EPB, e_end = min(s + EPB, NEDGE);
    for (int e = s + tid; e < e_end; e += 256) {
        int r = et[e], d = dst[e];
        int pos = atomicAdd(&cur[r], 1);
        g_srcP[pos]  = src[e];
        g_dstP[pos]  = d;
        g_normP[pos] = 1.0f / (float)max(g_cnt[d * NREL + r], 1);
    }
}

// ---------------------------------------------------------------- self-loop GEMM: O = X @ Wl
__global__ void __launch_bounds__(256) k_selfloop(const float* __restrict__ X,
                                                  const float* __restrict__ Wl,
                                                  float* __restrict__ O) {
    extern __shared__ float sm[];
    float* Ws  = sm;           // 64*64
    float* XsT = sm + 4096;    // 64*TILE (transposed)
    int tid  = threadIdx.x;
    int base = blockIdx.x * TILE;

    const float4* Wr  = (const float4*)Wl;
    float4*       Ws4 = (float4*)Ws;
#pragma unroll
    for (int j = 0; j < 4; j++) Ws4[tid + j * 256] = Wr[tid + j * 256];

    int e = tid >> 1, half = tid & 1;
    int row = base + e;
    if (row < NNODE) {
        const float4* xr = (const float4*)(X + (long)row * DIM + half * 32);
#pragma unroll
        for (int j = 0; j < 8; j++) {
            float4 v = xr[j];
            int d = half * 32 + j * 4;
            XsT[(d + 0) * TILE + e] = v.x;
            XsT[(d + 1) * TILE + e] = v.y;
            XsT[(d + 2) * TILE + e] = v.z;
            XsT[(d + 3) * TILE + e] = v.w;
        }
    } else {
#pragma unroll
        for (int j = 0; j < 8; j++) {
            int d = half * 32 + j * 4;
            XsT[(d + 0) * TILE + e] = 0.f; XsT[(d + 1) * TILE + e] = 0.f;
            XsT[(d + 2) * TILE + e] = 0.f; XsT[(d + 3) * TILE + e] = 0.f;
        }
    }
    __syncthreads();

    int tx = tid & 15, ty = tid >> 4;
    float4 acc[8];
#pragma unroll
    for (int i = 0; i < 8; i++) acc[i] = make_float4(0.f, 0.f, 0.f, 0.f);
#pragma unroll 8
    for (int k = 0; k < DIM; k++) {
        float4 b  = *(const float4*)&Ws[k * DIM + tx * 4];
        float4 a0 = *(const float4*)&XsT[k * TILE + ty * 8];
        float4 a1 = *(const float4*)&XsT[k * TILE + ty * 8 + 4];
        float av[8] = {a0.x, a0.y, a0.z, a0.w, a1.x, a1.y, a1.z, a1.w};
#pragma unroll
        for (int i = 0; i < 8; i++) {
            acc[i].x += av[i] * b.x;
            acc[i].y += av[i] * b.y;
            acc[i].z += av[i] * b.z;
            acc[i].w += av[i] * b.w;
        }
    }
#pragma unroll
    for (int i = 0; i < 8; i++) {
        int row2 = base + ty * 8 + i;
        if (row2 < NNODE)
            *(float4*)&O[(long)row2 * DIM + tx * 4] = acc[i];
    }
}

// ---------------------------------------------------------------- edge gather-MMA-scatter (3xTF32)
__global__ void __launch_bounds__(128) k_edges(const float* __restrict__ X,
                                               const float* __restrict__ W,
                                               float* __restrict__ O) {
    int t = blockIdx.x;
    if (t >= g_numTiles) return;
    int r  = g_tileRel[t];
    int s0 = g_tileStart[t];
    int m  = min(g_relOff[r + 1] - s0, TILE);

    extern __shared__ float sm[];
    float* Ahi = sm;                       // 128*SA
    float* Alo = Ahi + TILE * SA;          // 128*SA
    float* Whi = Alo + TILE * SA;          // 64*SA
    float* Wlo = Whi + DIM * SA;           // 64*SA
    int*   sDst = (int*)(Wlo + DIM * SA);  // 128

    int tid = threadIdx.x;

    // ---- load + split W[r] ----
    {
        const float4* Wr = (const float4*)(W + (long)r * DIM * DIM);
#pragma unroll
        for (int it = 0; it < 8; it++) {
            int i = tid + it * 128;             // 1024 float4 total
            float4 v = Wr[i];
            int row = i >> 4, col = (i & 15) * 4;
            float4 hi, lo;
            hi.x = __uint_as_float(f2tf(v.x)); lo.x = __uint_as_float(f2tf(v.x - hi.x));
            hi.y = __uint_as_float(f2tf(v.y)); lo.y = __uint_as_float(f2tf(v.y - hi.y));
            hi.z = __uint_as_float(f2tf(v.z)); lo.z = __uint_as_float(f2tf(v.z - hi.z));
            hi.w = __uint_as_float(f2tf(v.w)); lo.w = __uint_as_float(f2tf(v.w - hi.w));
            *(float4*)&Whi[row * SA + col] = hi;
            *(float4*)&Wlo[row * SA + col] = lo;
        }
    }

    // ---- gather + split A (one edge row per thread) ----
    {
        int e = tid;
        if (e < m) {
            sDst[e] = g_dstP[s0 + e];
            int   sr  = g_srcP[s0 + e];
            float nrm = g_normP[s0 + e];
            const float4* xr = (const float4*)(X + (long)sr * DIM);
#pragma unroll
            for (int j = 0; j < 16; j++) {
                float4 v = xr[j];
                v.x *= nrm; v.y *= nrm; v.z *= nrm; v.w *= nrm;
                float4 hi, lo;
                hi.x = __uint_as_float(f2tf(v.x)); lo.x = __uint_as_float(f2tf(v.x - hi.x));
                hi.y = __uint_as_float(f2tf(v.y)); lo.y = __uint_as_float(f2tf(v.y - hi.y));
                hi.z = __uint_as_float(f2tf(v.z)); lo.z = __uint_as_float(f2tf(v.z - hi.z));
                hi.w = __uint_as_float(f2tf(v.w)); lo.w = __uint_as_float(f2tf(v.w - hi.w));
                *(float4*)&Ahi[e * SA + j * 4] = hi;
                *(float4*)&Alo[e * SA + j * 4] = lo;
            }
        } else {
            float4 z = make_float4(0.f, 0.f, 0.f, 0.f);
#pragma unroll
            for (int j = 0; j < 16; j++) {
                *(float4*)&Ahi[e * SA + j * 4] = z;
                *(float4*)&Alo[e * SA + j * 4] = z;
            }
        }
    }
    __syncthreads();

    // ---- 3xTF32 MMA mainloop: per warp M=32, N=64, K=64 ----
    int lane = tid & 31, w = tid >> 5;
    int g = lane >> 2, tg = lane & 3;
    int mrow0 = w * 32;

    float c[2][8][4];
#pragma unroll
    for (int mt = 0; mt < 2; mt++)
#pragma unroll
        for (int n = 0; n < 8; n++) {
            c[mt][n][0] = 0.f; c[mt][n][1] = 0.f; c[mt][n][2] = 0.f; c[mt][n][3] = 0.f;
        }

#pragma unroll
    for (int ks = 0; ks < 8; ks++) {
        int k0 = ks * 8;
        unsigned ahi[2][4], alo[2][4];
#pragma unroll
        for (int mt = 0; mt < 2; mt++) {
            int base = (mrow0 + mt * 16 + g) * SA + k0 + tg;
            ahi[mt][0] = __float_as_uint(Ahi[base]);
            ahi[mt][1] = __float_as_uint(Ahi[base + 8 * SA]);
            ahi[mt][2] = __float_as_uint(Ahi[base + 4]);
            ahi[mt][3] = __float_as_uint(Ahi[base + 8 * SA + 4]);
            alo[mt][0] = __float_as_uint(Alo[base]);
            alo[mt][1] = __float_as_uint(Alo[base + 8 * SA]);
            alo[mt][2] = __float_as_uint(Alo[base + 4]);
            alo[mt][3] = __float_as_uint(Alo[base + 8 * SA + 4]);
        }
#pragma unroll
        for (int n = 0; n < 8; n++) {
            int nb = n * 8 + g;
            unsigned bhi0 = __float_as_uint(Whi[(k0 + tg) * SA + nb]);
            unsigned bhi1 = __float_as_uint(Whi[(k0 + tg + 4) * SA + nb]);
            unsigned blo0 = __float_as_uint(Wlo[(k0 + tg) * SA + nb]);
            unsigned blo1 = __float_as_uint(Wlo[(k0 + tg + 4) * SA + nb]);
#pragma unroll
            for (int mt = 0; mt < 2; mt++) {
                MMA_TF32(c[mt][n], ahi[mt], bhi0, bhi1);
                MMA_TF32(c[mt][n], ahi[mt], blo0, blo1);
                MMA_TF32(c[mt][n], alo[mt], bhi0, bhi1);
            }
        }
    }

    // ---- scatter: shfl-pair fragments into float4 red.global.add ----
    int  col0 = (tg & 2) * 2;         // 0 or 4 within the 8-wide n-tile
    bool lead = (tg & 1) == 0;
#pragma unroll
    for (int mt = 0; mt < 2; mt++) {
        int rA = mrow0 + mt * 16 + g;
        int rB = rA + 8;
        int dA = (rA < m) ? sDst[rA] : -1;
        int dB = (rB < m) ? sDst[rB] : -1;
#pragma unroll
        for (int n = 0; n < 8; n++) {
            float x0 = c[mt][n][0], y0 = c[mt][n][1];
            float x1 = c[mt][n][2], y1 = c[mt][n][3];
            float qx0 = __shfl_xor_sync(0xffffffffu, x0, 1);
            float qy0 = __shfl_xor_sync(0xffffffffu, y0, 1);
            float qx1 = __shfl_xor_sync(0xffffffffu, x1, 1);
            float qy1 = __shfl_xor_sync(0xffffffffu, y1, 1);
            if (lead && dA >= 0) {
                float* o = O + (long)dA * DIM + n * 8 + col0;
                asm volatile("red.global.add.v4.f32 [%0], {%1,%2,%3,%4};"
                             :: "l"(o), "f"(x0), "f"(y0), "f"(qx0), "f"(qy0) : "memory");
            }
            if (lead && dB >= 0) {
                float* o = O + (long)dB * DIM + n * 8 + col0;
                asm volatile("red.global.add.v4.f32 [%0], {%1,%2,%3,%4};"
                             :: "l"(o), "f"(x1), "f"(y1), "f"(qx1), "f"(qy1) : "memory");
            }
        }
    }
}

// ---------------------------------------------------------------- relu
__global__ void k_relu(float* __restrict__ O, int n4) {
    int i = blockIdx.x * blockDim.x + threadIdx.x;
    if (i < n4) {
        float4 v = ((float4*)O)[i];
        v.x = fmaxf(v.x, 0.f); v.y = fmaxf(v.y, 0.f);
        v.z = fmaxf(v.z, 0.f); v.w = fmaxf(v.w, 0.f);
        ((float4*)O)[i] = v;
    }
}

// ---------------------------------------------------------------- launch
extern "C" void kernel_launch(void* const* d_in, const int* in_sizes, int n_in,
                              void* d_out, int out_size) {
    const float* x   = (const float*)d_in[0];
    const int*   src = (const int*)d_in[1];
    const int*   dst = (const int*)d_in[2];
    const int*   et  = (const int*)d_in[3];
    const float* W1  = (const float*)d_in[4];
    const float* Wl1 = (const float*)d_in[5];
    const float* W2  = (const float*)d_in[6];
    const float* Wl2 = (const float*)d_in[7];
    float* out = (float*)d_out;

    void* hsym = nullptr;
    cudaGetSymbolAddress(&hsym, g_h);
    float* h = (float*)hsym;

    const int EDGE_SMEM = (2 * TILE * SA + 2 * DIM * SA) * 4 + TILE * 4;  // 104960
    cudaFuncSetAttribute(k_edges,    cudaFuncAttributeMaxDynamicSharedMemorySize, EDGE_SMEM);
    cudaFuncSetAttribute(k_selfloop, cudaFuncAttributeMaxDynamicSharedMemorySize, 49152);

    const int TPB = 256;
    // preprocessing: contention-free counting sort by relation
    k_zero<<<(NNODE * NREL / 4 + TPB - 1) / TPB, TPB>>>();
    k_hist<<<NB, TPB>>>(dst, et);
    k_scanRel<<<NREL, 256>>>();
    k_scan<<<1, 32>>>();
    k_tiles<<<(NTILES_MAX + 127) / 128, 128>>>();
    k_scatter<<<NB, TPB>>>(src, dst, et);

    int nBlocksRows = (NNODE + TILE - 1) / TILE;
    int n4 = NNODE * DIM / 4;

    // layer 1: h = relu(edges(x,W1) + x@Wl1)
    k_selfloop<<<nBlocksRows, TPB, 49152>>>(x, Wl1, h);
    k_edges<<<NTILES_MAX, 128, EDGE_SMEM>>>(x, W1, h);
    k_relu<<<(n4 + TPB - 1) / TPB, TPB>>>(h, n4);

    // layer 2: out = relu(edges(h,W2) + h@Wl2)
    k_selfloop<<<nBlocksRows, TPB, 49152>>>(h, Wl2, out);
    k_edges<<<NTILES_MAX, 128, EDGE_SMEM>>>(h, W2, out);
    k_relu<<<(n4 + TPB - 1) / TPB, TPB>>>(out, n4);
}

// round 5
// speedup vs baseline: 1.1860x; 1.1860x over previous
#include <cuda_runtime.h>
#include <cuda_bf16.h>
#include <cstdint>

#define NNODE 50000
#define NEDGE 800000
#define DIM   64
#define NREL  65
#define TILE  128
#define EPB   2048
#define NB    ((NEDGE + EPB - 1) / EPB)
#define NTILES_MAX ((NEDGE + TILE - 1) / TILE + NREL)
#define SAK   72    // A smem row stride in bf16 units (conflict-free: 36 words = 4 mod 32)
#define SBK   72    // B smem row stride in bf16 units

// ---- scratch (static device globals; no allocation) ----
__device__ int   g_cnt[NNODE * NREL];
__device__ int   g_blockHist[NB * NREL];
__device__ int   g_relCnt[NREL];
__device__ int   g_relOff[NREL + 1];
__device__ int   g_tileBase[NREL + 1];
__device__ int   g_tileRel[NTILES_MAX];
__device__ int   g_tileStart[NTILES_MAX];
__device__ int   g_numTiles;
__device__ int   g_srcP[NEDGE];
__device__ int   g_dstP[NEDGE];
__device__ float g_normP[NEDGE];
__device__ float g_h[NNODE * DIM];

#define MMA_BF16(c, a, b0, b1)                                                   \
    asm volatile("mma.sync.aligned.m16n8k16.row.col.f32.bf16.bf16.f32 "          \
                 "{%0,%1,%2,%3},{%4,%5,%6,%7},{%8,%9},{%0,%1,%2,%3};"            \
                 : "+f"(c[0]), "+f"(c[1]), "+f"(c[2]), "+f"(c[3])                \
                 : "r"(a[0]), "r"(a[1]), "r"(a[2]), "r"(a[3]), "r"(b0), "r"(b1))

// SMEM layout (bytes)
#define SM_DST  0
#define SM_AH   512
#define SM_AL   (SM_AH + TILE * SAK * 2)     // +18432
#define SM_BH   (SM_AL + TILE * SAK * 2)
#define SM_BL   (SM_BH + DIM * SBK * 2)      // +9216
#define SM_TOT  (SM_BL + DIM * SBK * 2)      // 55808

// ---------------------------------------------------------------- zero g_cnt
__global__ void k_zero() {
    int i = blockIdx.x * blockDim.x + threadIdx.x;
    if (i < NNODE * NREL / 4) {
        int4 z = make_int4(0, 0, 0, 0);
        ((int4*)g_cnt)[i] = z;
    }
}

// ---------------------------------------------------------------- histogram
__global__ void __launch_bounds__(256) k_hist(const int* __restrict__ dst,
                                              const int* __restrict__ et) {
    __shared__ int h[NREL];
    int tid = threadIdx.x, b = blockIdx.x;
    if (tid < NREL) h[tid] = 0;
    __syncthreads();
    int s = b * EPB, e_end = min(s + EPB, NEDGE);
    for (int e = s + tid; e < e_end; e += 256) {
        int r = et[e];
        atomicAdd(&h[r], 1);
        atomicAdd(&g_cnt[dst[e] * NREL + r], 1);
    }
    __syncthreads();
    if (tid < NREL) g_blockHist[b * NREL + tid] = h[tid];
}

// ---------------------------------------------------------------- per-relation block scan
__global__ void k_scanRel() {
    __shared__ int v[NB];
    int r = blockIdx.x, tid = threadIdx.x;
    for (int b = tid; b < NB; b += blockDim.x) v[b] = g_blockHist[b * NREL + r];
    __syncthreads();
    if (tid == 0) {
        int acc = 0;
        for (int b = 0; b < NB; b++) { int t = v[b]; v[b] = acc; acc += t; }
        g_relCnt[r] = acc;
    }
    __syncthreads();
    for (int b = tid; b < NB; b += blockDim.x) g_blockHist[b * NREL + r] = v[b];
}

// ---------------------------------------------------------------- relation offsets
__global__ void k_scan() {
    if (threadIdx.x == 0) {
        int eo = 0, to = 0;
        for (int r = 0; r < NREL; r++) {
            g_relOff[r] = eo; g_tileBase[r] = to;
            int c = g_relCnt[r];
            eo += c;
            to += (c + TILE - 1) / TILE;
        }
        g_relOff[NREL] = eo;
        g_tileBase[NREL] = to;
        g_numTiles = to;
    }
}

// ---------------------------------------------------------------- parallel tile table
__global__ void k_tiles() {
    int t = blockIdx.x * blockDim.x + threadIdx.x;
    if (t >= g_numTiles) return;
    int lo = 0, hi = NREL;
    while (lo + 1 < hi) {
        int mid = (lo + hi) >> 1;
        if (g_tileBase[mid] <= t) lo = mid; else hi = mid;
    }
    g_tileRel[t]   = lo;
    g_tileStart[t] = g_relOff[lo] + (t - g_tileBase[lo]) * TILE;
}

// ---------------------------------------------------------------- scatter sorted arrays
__global__ void __launch_bounds__(256) k_scatter(const int* __restrict__ src,
                                                 const int* __restrict__ dst,
                                                 const int* __restrict__ et) {
    __shared__ int cur[NREL];
    int tid = threadIdx.x, b = blockIdx.x;
    if (tid < NREL) cur[tid] = g_relOff[tid] + g_blockHist[b * NREL + tid];
    __syncthreads();
    int s = b * EPB, e_end = min(s + EPB, NEDGE);
    for (int e = s + tid; e < e_end; e += 256) {
        int r = et[e], d = dst[e];
        int pos = atomicAdd(&cur[r], 1);
        g_srcP[pos]  = src[e];
        g_dstP[pos]  = d;
        g_normP[pos] = 1.0f / (float)max(g_cnt[d * NREL + r], 1);
    }
}

// ---------------------------------------------------------------- self-loop GEMM: O = X @ Wl
__global__ void __launch_bounds__(256) k_selfloop(const float* __restrict__ X,
                                                  const float* __restrict__ Wl,
                                                  float* __restrict__ O) {
    extern __shared__ float sm[];
    float* Ws  = sm;
    float* XsT = sm + 4096;
    int tid  = threadIdx.x;
    int base = blockIdx.x * TILE;

    const float4* Wr  = (const float4*)Wl;
    float4*       Ws4 = (float4*)Ws;
#pragma unroll
    for (int j = 0; j < 4; j++) Ws4[tid + j * 256] = Wr[tid + j * 256];

    int e = tid >> 1, half = tid & 1;
    int row = base + e;
    if (row < NNODE) {
        const float4* xr = (const float4*)(X + (long)row * DIM + half * 32);
#pragma unroll
        for (int j = 0; j < 8; j++) {
            float4 v = xr[j];
            int d = half * 32 + j * 4;
            XsT[(d + 0) * TILE + e] = v.x;
            XsT[(d + 1) * TILE + e] = v.y;
            XsT[(d + 2) * TILE + e] = v.z;
            XsT[(d + 3) * TILE + e] = v.w;
        }
    } else {
#pragma unroll
        for (int j = 0; j < 8; j++) {
            int d = half * 32 + j * 4;
            XsT[(d + 0) * TILE + e] = 0.f; XsT[(d + 1) * TILE + e] = 0.f;
            XsT[(d + 2) * TILE + e] = 0.f; XsT[(d + 3) * TILE + e] = 0.f;
        }
    }
    __syncthreads();

    int tx = tid & 15, ty = tid >> 4;
    float4 acc[8];
#pragma unroll
    for (int i = 0; i < 8; i++) acc[i] = make_float4(0.f, 0.f, 0.f, 0.f);
#pragma unroll 8
    for (int k = 0; k < DIM; k++) {
        float4 b  = *(const float4*)&Ws[k * DIM + tx * 4];
        float4 a0 = *(const float4*)&XsT[k * TILE + ty * 8];
        float4 a1 = *(const float4*)&XsT[k * TILE + ty * 8 + 4];
        float av[8] = {a0.x, a0.y, a0.z, a0.w, a1.x, a1.y, a1.z, a1.w};
#pragma unroll
        for (int i = 0; i < 8; i++) {
            acc[i].x += av[i] * b.x;
            acc[i].y += av[i] * b.y;
            acc[i].z += av[i] * b.z;
            acc[i].w += av[i] * b.w;
        }
    }
#pragma unroll
    for (int i = 0; i < 8; i++) {
        int row2 = base + ty * 8 + i;
        if (row2 < NNODE)
            *(float4*)&O[(long)row2 * DIM + tx * 4] = acc[i];
    }
}

// ---------------------------------------------------------------- edge kernel: bf16 HMMA 3-term
__global__ void __launch_bounds__(256, 3) k_edges(const float* __restrict__ X,
                                                  const float* __restrict__ W,
                                                  float* __restrict__ O) {
    int t = blockIdx.x;
    if (t >= g_numTiles) return;
    int r  = g_tileRel[t];
    int s0 = g_tileStart[t];
    int m  = min(g_relOff[r + 1] - s0, TILE);

    extern __shared__ char smem[];
    int*            sDst = (int*)(smem + SM_DST);
    __nv_bfloat16*  Ahi  = (__nv_bfloat16*)(smem + SM_AH);
    __nv_bfloat16*  Alo  = (__nv_bfloat16*)(smem + SM_AL);
    __nv_bfloat16*  Bhi  = (__nv_bfloat16*)(smem + SM_BH);
    __nv_bfloat16*  Blo  = (__nv_bfloat16*)(smem + SM_BL);
    int tid = threadIdx.x;

    // ---- B[n][k] = W[r][k][n], split hi/lo bf16 ----
    {
        const float4* Wr = (const float4*)(W + (long)r * DIM * DIM);
#pragma unroll
        for (int j = 0; j < 4; j++) {
            int i4 = tid + j * 256;             // 1024 float4 total
            float4 v = Wr[i4];
            int k = i4 >> 4, n0 = (i4 & 15) * 4;
            float vv[4] = {v.x, v.y, v.z, v.w};
#pragma unroll
            for (int p = 0; p < 4; p++) {
                __nv_bfloat16 h = __float2bfloat16_rn(vv[p]);
                __nv_bfloat16 l = __float2bfloat16_rn(vv[p] - __bfloat162float(h));
                Bhi[(n0 + p) * SBK + k] = h;
                Blo[(n0 + p) * SBK + k] = l;
            }
        }
    }

    // ---- A = gathered, norm-scaled rows, split hi/lo bf16 ----
    {
        int e = tid >> 1, half = tid & 1;
        uint32_t rowOff = (uint32_t)e * SAK * 2 + half * 64;
        if (e < m) {
            int   sr  = g_srcP[s0 + e];
            float nrm = g_normP[s0 + e];
            if (half == 0) sDst[e] = g_dstP[s0 + e];
            const float4* xr = (const float4*)(X + (long)sr * DIM + half * 32);
#pragma unroll
            for (int j = 0; j < 8; j++) {
                float4 v = xr[j];
                v.x *= nrm; v.y *= nrm; v.z *= nrm; v.w *= nrm;
                __nv_bfloat162 h0 = __float22bfloat162_rn(make_float2(v.x, v.y));
                __nv_bfloat162 h1 = __float22bfloat162_rn(make_float2(v.z, v.w));
                float2 f0 = __bfloat1622float2(h0);
                float2 f1 = __bfloat1622float2(h1);
                __nv_bfloat162 l0 = __float22bfloat162_rn(make_float2(v.x - f0.x, v.y - f0.y));
                __nv_bfloat162 l1 = __float22bfloat162_rn(make_float2(v.z - f1.x, v.w - f1.y));
                *(uint2*)((char*)Ahi + rowOff + j * 8) =
                    make_uint2(*(uint32_t*)&h0, *(uint32_t*)&h1);
                *(uint2*)((char*)Alo + rowOff + j * 8) =
                    make_uint2(*(uint32_t*)&l0, *(uint32_t*)&l1);
            }
        } else {
            uint2 z = make_uint2(0u, 0u);
#pragma unroll
            for (int j = 0; j < 8; j++) {
                *(uint2*)((char*)Ahi + rowOff + j * 8) = z;
                *(uint2*)((char*)Alo + rowOff + j * 8) = z;
            }
        }
    }
    __syncthreads();

    // ---- mainloop: 8 warps, each M=16 rows; 4 k-steps x 8 n-tiles x 3 terms ----
    int lane = tid & 31, wid = tid >> 5;
    int g = lane >> 2, tg = lane & 3;
    int m0 = wid * 16;

    float c[8][4];
#pragma unroll
    for (int n = 0; n < 8; n++) {
        c[n][0] = 0.f; c[n][1] = 0.f; c[n][2] = 0.f; c[n][3] = 0.f;
    }

#pragma unroll
    for (int ks = 0; ks < 4; ks++) {
        int k0 = ks * 16;
        uint32_t ah[4], al[4];
        {
            const char* pLo = (const char*)Ahi + ((m0 + g) * SAK + k0 + 2 * tg) * 2;
            const char* pHi = pLo + 8 * SAK * 2;
            ah[0] = *(const uint32_t*)pLo;
            ah[1] = *(const uint32_t*)pHi;
            ah[2] = *(const uint32_t*)(pLo + 16);
            ah[3] = *(const uint32_t*)(pHi + 16);
            const char* qLo = (const char*)Alo + ((m0 + g) * SAK + k0 + 2 * tg) * 2;
            const char* qHi = qLo + 8 * SAK * 2;
            al[0] = *(const uint32_t*)qLo;
            al[1] = *(const uint32_t*)qHi;
            al[2] = *(const uint32_t*)(qLo + 16);
            al[3] = *(const uint32_t*)(qHi + 16);
        }
#pragma unroll
        for (int n = 0; n < 8; n++) {
            int colb = n * 8 + g;
            uint32_t off = (uint32_t)(colb * SBK + k0 + 2 * tg) * 2;
            uint32_t bh0 = *(const uint32_t*)((const char*)Bhi + off);
            uint32_t bh1 = *(const uint32_t*)((const char*)Bhi + off + 16);
            uint32_t bl0 = *(const uint32_t*)((const char*)Blo + off);
            uint32_t bl1 = *(const uint32_t*)((const char*)Blo + off + 16);
            MMA_BF16(c[n], ah, bh0, bh1);
            MMA_BF16(c[n], al, bh0, bh1);
            MMA_BF16(c[n], ah, bl0, bl1);
        }
    }

    // ---- scatter: shfl-pair fragments into float4 red.global.add ----
    int  col0 = (tg & 2) * 2;
    bool lead = (tg & 1) == 0;
    int rA = m0 + g;
    int rB = rA + 8;
    int dA = (rA < m) ? sDst[rA] : -1;
    int dB = (rB < m) ? sDst[rB] : -1;
#pragma unroll
    for (int n = 0; n < 8; n++) {
        float x0 = c[n][0], y0 = c[n][1];
        float x1 = c[n][2], y1 = c[n][3];
        float qx0 = __shfl_xor_sync(0xffffffffu, x0, 1);
        float qy0 = __shfl_xor_sync(0xffffffffu, y0, 1);
        float qx1 = __shfl_xor_sync(0xffffffffu, x1, 1);
        float qy1 = __shfl_xor_sync(0xffffffffu, y1, 1);
        if (lead && dA >= 0) {
            float* o = O + (long)dA * DIM + n * 8 + col0;
            asm volatile("red.global.add.v4.f32 [%0], {%1,%2,%3,%4};"
                         :: "l"(o), "f"(x0), "f"(y0), "f"(qx0), "f"(qy0) : "memory");
        }
        if (lead && dB >= 0) {
            float* o = O + (long)dB * DIM + n * 8 + col0;
            asm volatile("red.global.add.v4.f32 [%0], {%1,%2,%3,%4};"
                         :: "l"(o), "f"(x1), "f"(y1), "f"(qx1), "f"(qy1) : "memory");
        }
    }
}

// ---------------------------------------------------------------- relu
__global__ void k_relu(float* __restrict__ O, int n4) {
    int i = blockIdx.x * blockDim.x + threadIdx.x;
    if (i < n4) {
        float4 v = ((float4*)O)[i];
        v.x = fmaxf(v.x, 0.f); v.y = fmaxf(v.y, 0.f);
        v.z = fmaxf(v.z, 0.f); v.w = fmaxf(v.w, 0.f);
        ((float4*)O)[i] = v;
    }
}

// ---------------------------------------------------------------- launch
extern "C" void kernel_launch(void* const* d_in, const int* in_sizes, int n_in,
                              void* d_out, int out_size) {
    const float* x   = (const float*)d_in[0];
    const int*   src = (const int*)d_in[1];
    const int*   dst = (const int*)d_in[2];
    const int*   et  = (const int*)d_in[3];
    const float* W1  = (const float*)d_in[4];
    const float* Wl1 = (const float*)d_in[5];
    const float* W2  = (const float*)d_in[6];
    const float* Wl2 = (const float*)d_in[7];
    float* out = (float*)d_out;

    void* hsym = nullptr;
    cudaGetSymbolAddress(&hsym, g_h);
    float* h = (float*)hsym;

    cudaFuncSetAttribute(k_edges,    cudaFuncAttributeMaxDynamicSharedMemorySize, SM_TOT);
    cudaFuncSetAttribute(k_selfloop, cudaFuncAttributeMaxDynamicSharedMemorySize, 49152);

    const int TPB = 256;
    // preprocessing: contention-free counting sort by relation
    k_zero<<<(NNODE * NREL / 4 + TPB - 1) / TPB, TPB>>>();
    k_hist<<<NB, TPB>>>(dst, et);
    k_scanRel<<<NREL, 256>>>();
    k_scan<<<1, 32>>>();
    k_tiles<<<(NTILES_MAX + 127) / 128, 128>>>();
    k_scatter<<<NB, TPB>>>(src, dst, et);

    int nBlocksRows = (NNODE + TILE - 1) / TILE;
    int n4 = NNODE * DIM / 4;

    // layer 1: h = relu(edges(x,W1) + x@Wl1)
    k_selfloop<<<nBlocksRows, TPB, 49152>>>(x, Wl1, h);
    k_edges<<<NTILES_MAX, TPB, SM_TOT>>>(x, W1, h);
    k_relu<<<(n4 + TPB - 1) / TPB, TPB>>>(h, n4);

    // layer 2: out = relu(edges(h,W2) + h@Wl2)
    k_selfloop<<<nBlocksRows, TPB, 49152>>>(h, Wl2, out);
    k_edges<<<NTILES_MAX, TPB, SM_TOT>>>(h, W2, out);
    k_relu<<<(n4 + TPB - 1) / TPB, TPB>>>(out, n4);
}

// round 6
// speedup vs baseline: 1.5805x; 1.3327x over previous
#include <cuda_runtime.h>
#include <cuda_bf16.h>
#include <cstdint>

#define NNODE 50000
#define NEDGE 800000
#define DIM   64
#define NREL  65
#define TILE  128
#define EPB   2048
#define NB    ((NEDGE + EPB - 1) / EPB)
#define NTILES_MAX ((NEDGE + TILE - 1) / TILE + NREL)
#define SAK   72    // A smem row stride in bf16 units
#define SBK   72    // B smem row stride in bf16 units

// ---- scratch (static device globals; no allocation) ----
__device__ int   g_cnt[NNODE * NREL];
__device__ int   g_blockHist[NB * NREL];
__device__ int   g_relCnt[NREL];
__device__ int   g_relOff[NREL + 1];
__device__ int   g_tileBase[NREL + 1];
__device__ int   g_tileRel[NTILES_MAX];
__device__ int   g_tileStart[NTILES_MAX];
__device__ int   g_numTiles;
__device__ int   g_srcP[NEDGE];
__device__ int   g_dstP[NEDGE];
__device__ float g_normP[NEDGE];
__device__ float g_h[NNODE * DIM];
// pre-split bf16 buffers: row = 128 bf16 (hi[0:64], lo[64:128]) = 256B
__device__ __nv_bfloat16 g_Xs[(size_t)NNODE * 128];
__device__ __nv_bfloat16 g_Hs[(size_t)NNODE * 128];
// W splits: 66 slots (65 relations + self-loop W), [slot][n][128]: hi(k) 0:64, lo(k) 64:128
__device__ __nv_bfloat16 g_Ws1[(size_t)(NREL + 1) * DIM * 128];
__device__ __nv_bfloat16 g_Ws2[(size_t)(NREL + 1) * DIM * 128];

#define MMA_BF16(c, a, b0, b1)                                                   \
    asm volatile("mma.sync.aligned.m16n8k16.row.col.f32.bf16.bf16.f32 "          \
                 "{%0,%1,%2,%3},{%4,%5,%6,%7},{%8,%9},{%0,%1,%2,%3};"            \
                 : "+f"(c[0]), "+f"(c[1]), "+f"(c[2]), "+f"(c[3])                \
                 : "r"(a[0]), "r"(a[1]), "r"(a[2]), "r"(a[3]), "r"(b0), "r"(b1))

// SMEM layout (bytes)
#define SM_DST  0
#define SM_NRM  512
#define SM_AH   1024
#define SM_AL   (SM_AH + TILE * SAK * 2 + 16)   // 19472
#define SM_BH   (SM_AL + TILE * SAK * 2 + 16)   // 37920
#define SM_BL   (SM_BH + DIM * SBK * 2 + 16)    // 47152
#define SM_TOT  (SM_BL + DIM * SBK * 2)         // 56368

// ---------------------------------------------------------------- zero g_cnt
__global__ void k_zero() {
    int i = blockIdx.x * blockDim.x + threadIdx.x;
    if (i < NNODE * NREL / 4) {
        int4 z = make_int4(0, 0, 0, 0);
        ((int4*)g_cnt)[i] = z;
    }
}

// ---------------------------------------------------------------- histogram
__global__ void __launch_bounds__(256) k_hist(const int* __restrict__ dst,
                                              const int* __restrict__ et) {
    __shared__ int h[NREL];
    int tid = threadIdx.x, b = blockIdx.x;
    if (tid < NREL) h[tid] = 0;
    __syncthreads();
    int s = b * EPB, e_end = min(s + EPB, NEDGE);
    for (int e = s + tid; e < e_end; e += 256) {
        int r = et[e];
        atomicAdd(&h[r], 1);
        atomicAdd(&g_cnt[dst[e] * NREL + r], 1);
    }
    __syncthreads();
    if (tid < NREL) g_blockHist[b * NREL + tid] = h[tid];
}

// ---------------------------------------------------------------- per-relation block scan
__global__ void k_scanRel() {
    __shared__ int v[NB];
    int r = blockIdx.x, tid = threadIdx.x;
    for (int b = tid; b < NB; b += blockDim.x) v[b] = g_blockHist[b * NREL + r];
    __syncthreads();
    if (tid == 0) {
        int acc = 0;
        for (int b = 0; b < NB; b++) { int t = v[b]; v[b] = acc; acc += t; }
        g_relCnt[r] = acc;
    }
    __syncthreads();
    for (int b = tid; b < NB; b += blockDim.x) g_blockHist[b * NREL + r] = v[b];
}

// ---------------------------------------------------------------- relation offsets (parallel scan)
__global__ void k_scan() {
    __shared__ int a[128], b2[128];
    int t = threadIdx.x;
    int c  = (t < NREL) ? g_relCnt[t] : 0;
    int nt = (c + TILE - 1) / TILE;
    a[t] = c; b2[t] = nt;
    __syncthreads();
    for (int off = 1; off < 128; off <<= 1) {
        int av = a[t], bv = b2[t];
        int au = (t >= off) ? a[t - off] : 0;
        int bu = (t >= off) ? b2[t - off] : 0;
        __syncthreads();
        a[t] = av + au; b2[t] = bv + bu;
        __syncthreads();
    }
    if (t < NREL) { g_relOff[t] = a[t] - c; g_tileBase[t] = b2[t] - nt; }
    if (t == NREL - 1) {
        g_relOff[NREL] = a[t];
        g_tileBase[NREL] = b2[t];
        g_numTiles = b2[t];
    }
}

// ---------------------------------------------------------------- parallel tile table
__global__ void k_tiles() {
    int t = blockIdx.x * blockDim.x + threadIdx.x;
    if (t >= g_numTiles) return;
    int lo = 0, hi = NREL;
    while (lo + 1 < hi) {
        int mid = (lo + hi) >> 1;
        if (g_tileBase[mid] <= t) lo = mid; else hi = mid;
    }
    g_tileRel[t]   = lo;
    g_tileStart[t] = g_relOff[lo] + (t - g_tileBase[lo]) * TILE;
}

// ---------------------------------------------------------------- scatter sorted arrays
__global__ void __launch_bounds__(256) k_scatter(const int* __restrict__ src,
                                                 const int* __restrict__ dst,
                                                 const int* __restrict__ et) {
    __shared__ int cur[NREL];
    int tid = threadIdx.x, b = blockIdx.x;
    if (tid < NREL) cur[tid] = g_relOff[tid] + g_blockHist[b * NREL + tid];
    __syncthreads();
    int s = b * EPB, e_end = min(s + EPB, NEDGE);
    for (int e = s + tid; e < e_end; e += 256) {
        int r = et[e], d = dst[e];
        int pos = atomicAdd(&cur[r], 1);
        g_srcP[pos]  = src[e];
        g_dstP[pos]  = d;
        g_normP[pos] = 1.0f / (float)max(g_cnt[d * NREL + r], 1);
    }
}

// ---------------------------------------------------------------- W split: [k][n] fp32 -> [n][hi|lo] bf16
__global__ void __launch_bounds__(256) k_wsplit(const float* __restrict__ W,
                                                const float* __restrict__ Wl,
                                                __nv_bfloat16* __restrict__ out) {
    int r = blockIdx.x;                               // 0..NREL (NREL = self-loop slot)
    const float* src = (r < NREL) ? (W + (size_t)r * DIM * DIM) : Wl;
    int t = threadIdx.x;
    int n = t >> 2, kc = (t & 3) * 16;
    __nv_bfloat16 h[16], l[16];
#pragma unroll
    for (int kk = 0; kk < 16; kk++) {
        float v = src[(kc + kk) * DIM + n];
        __nv_bfloat16 hh = __float2bfloat16_rn(v);
        h[kk] = hh;
        l[kk] = __float2bfloat16_rn(v - __bfloat162float(hh));
    }
    __nv_bfloat16* o = out + ((size_t)(r * DIM + n) * 128 + kc);
    *(uint4*)o        = *(uint4*)&h[0];
    *(uint4*)(o + 8)  = *(uint4*)&h[8];
    *(uint4*)(o + 64) = *(uint4*)&l[0];
    *(uint4*)(o + 72) = *(uint4*)&l[8];
}

// ---------------------------------------------------------------- X split: fp32 row -> hi|lo bf16 row
__global__ void k_xsplit(const float* __restrict__ X, __nv_bfloat16* __restrict__ Xs) {
    int i = blockIdx.x * blockDim.x + threadIdx.x;
    if (i >= NNODE * 8) return;
    int row = i >> 3, seg = i & 7;
    const float4* p = (const float4*)(X + (size_t)row * DIM + seg * 8);
    float4 v0 = p[0], v1 = p[1];
    float vv[8] = {v0.x, v0.y, v0.z, v0.w, v1.x, v1.y, v1.z, v1.w};
    __nv_bfloat16 h[8], l[8];
#pragma unroll
    for (int j = 0; j < 8; j++) {
        __nv_bfloat16 hh = __float2bfloat16_rn(vv[j]);
        h[j] = hh;
        l[j] = __float2bfloat16_rn(vv[j] - __bfloat162float(hh));
    }
    __nv_bfloat16* o = Xs + (size_t)row * 128 + seg * 8;
    *(uint4*)o        = *(uint4*)h;
    *(uint4*)(o + 64) = *(uint4*)l;
}

// ---------------------------------------------------------------- relu + split (layer boundary)
__global__ void k_relu_split(const float* __restrict__ O, __nv_bfloat16* __restrict__ Xs) {
    int i = blockIdx.x * blockDim.x + threadIdx.x;
    if (i >= NNODE * 8) return;
    int row = i >> 3, seg = i & 7;
    const float4* p = (const float4*)(O + (size_t)row * DIM + seg * 8);
    float4 v0 = p[0], v1 = p[1];
    float vv[8] = {fmaxf(v0.x, 0.f), fmaxf(v0.y, 0.f), fmaxf(v0.z, 0.f), fmaxf(v0.w, 0.f),
                   fmaxf(v1.x, 0.f), fmaxf(v1.y, 0.f), fmaxf(v1.z, 0.f), fmaxf(v1.w, 0.f)};
    __nv_bfloat16 h[8], l[8];
#pragma unroll
    for (int j = 0; j < 8; j++) {
        __nv_bfloat16 hh = __float2bfloat16_rn(vv[j]);
        h[j] = hh;
        l[j] = __float2bfloat16_rn(vv[j] - __bfloat162float(hh));
    }
    __nv_bfloat16* o = Xs + (size_t)row * 128 + seg * 8;
    *(uint4*)o        = *(uint4*)h;
    *(uint4*)(o + 64) = *(uint4*)l;
}

// ---------------------------------------------------------------- self-loop via MMA: O = X @ Wl (written, not added)
__global__ void __launch_bounds__(256, 3) k_selfloop(const __nv_bfloat16* __restrict__ Xs,
                                                     const __nv_bfloat16* __restrict__ Ws,
                                                     float* __restrict__ O) {
    int base = blockIdx.x * TILE;
    int m = min(TILE, NNODE - base);
    extern __shared__ char smem[];
    int tid = threadIdx.x;

    // B from self-loop slot (r = NREL)
    {
        int n = tid >> 2, c = tid & 3;
        const uint4* wr = (const uint4*)(Ws + ((size_t)(NREL * DIM + n) * 128 + (c & 1) * 32 + (c >> 1) * 64));
        char* db = smem + ((c >> 1) ? SM_BL : SM_BH) + n * 144 + (c & 1) * 64;
#pragma unroll
        for (int j = 0; j < 4; j++) ((uint4*)db)[j] = wr[j];
    }
    // A: contiguous rows base..base+127
    {
        int e = tid >> 1, half = tid & 1;
        char* ah = smem + SM_AH + e * 144 + half * 64;
        char* al = smem + SM_AL + e * 144 + half * 64;
        if (e < m) {
            const uint4* xr = (const uint4*)(Xs + (size_t)(base + e) * 128);
#pragma unroll
            for (int j = 0; j < 4; j++) ((uint4*)ah)[j] = xr[half * 4 + j];
#pragma unroll
            for (int j = 0; j < 4; j++) ((uint4*)al)[j] = xr[8 + half * 4 + j];
        } else {
            uint4 z = make_uint4(0, 0, 0, 0);
#pragma unroll
            for (int j = 0; j < 4; j++) { ((uint4*)ah)[j] = z; ((uint4*)al)[j] = z; }
        }
    }
    __syncthreads();

    int lane = tid & 31, wid = tid >> 5;
    int g = lane >> 2, tg = lane & 3;
    int m0 = wid * 16;

    float c[8][4];
#pragma unroll
    for (int n = 0; n < 8; n++) { c[n][0] = 0.f; c[n][1] = 0.f; c[n][2] = 0.f; c[n][3] = 0.f; }

#pragma unroll
    for (int ks = 0; ks < 4; ks++) {
        int k0 = ks * 16;
        uint32_t ah[4], al[4];
        {
            const char* pLo = smem + SM_AH + ((m0 + g) * SAK + k0 + 2 * tg) * 2;
            const char* pHi = pLo + 8 * SAK * 2;
            ah[0] = *(const uint32_t*)pLo;  ah[1] = *(const uint32_t*)pHi;
            ah[2] = *(const uint32_t*)(pLo + 16); ah[3] = *(const uint32_t*)(pHi + 16);
            const char* qLo = smem + SM_AL + ((m0 + g) * SAK + k0 + 2 * tg) * 2;
            const char* qHi = qLo + 8 * SAK * 2;
            al[0] = *(const uint32_t*)qLo;  al[1] = *(const uint32_t*)qHi;
            al[2] = *(const uint32_t*)(qLo + 16); al[3] = *(const uint32_t*)(qHi + 16);
        }
#pragma unroll
        for (int n = 0; n < 8; n++) {
            uint32_t off = (uint32_t)((n * 8 + g) * SBK + k0 + 2 * tg) * 2;
            uint32_t bh0 = *(const uint32_t*)(smem + SM_BH + off);
            uint32_t bh1 = *(const uint32_t*)(smem + SM_BH + off + 16);
            uint32_t bl0 = *(const uint32_t*)(smem + SM_BL + off);
            uint32_t bl1 = *(const uint32_t*)(smem + SM_BL + off + 16);
            MMA_BF16(c[n], ah, bh0, bh1);
            MMA_BF16(c[n], al, bh0, bh1);
            MMA_BF16(c[n], ah, bl0, bl1);
        }
    }

    int  col0 = (tg & 2) * 2;
    bool lead = (tg & 1) == 0;
    int rA = m0 + g, rB = rA + 8;
    bool okA = rA < m, okB = rB < m;
#pragma unroll
    for (int n = 0; n < 8; n++) {
        float x0 = c[n][0], y0 = c[n][1];
        float x1 = c[n][2], y1 = c[n][3];
        float qx0 = __shfl_xor_sync(0xffffffffu, x0, 1);
        float qy0 = __shfl_xor_sync(0xffffffffu, y0, 1);
        float qx1 = __shfl_xor_sync(0xffffffffu, x1, 1);
        float qy1 = __shfl_xor_sync(0xffffffffu, y1, 1);
        if (lead && okA)
            *(float4*)(O + (size_t)(base + rA) * DIM + n * 8 + col0) = make_float4(x0, y0, qx0, qy0);
        if (lead && okB)
            *(float4*)(O + (size_t)(base + rB) * DIM + n * 8 + col0) = make_float4(x1, y1, qx1, qy1);
    }
}

// ---------------------------------------------------------------- edge kernel: pre-split gather-MMA-scatter
__global__ void __launch_bounds__(256, 3) k_edges(const __nv_bfloat16* __restrict__ Xs,
                                                  const __nv_bfloat16* __restrict__ Ws,
                                                  float* __restrict__ O) {
    int t = blockIdx.x;
    if (t >= g_numTiles) return;
    int r  = g_tileRel[t];
    int s0 = g_tileStart[t];
    int m  = min(g_relOff[r + 1] - s0, TILE);

    extern __shared__ char smem[];
    int*   sDst  = (int*)(smem + SM_DST);
    float* sNorm = (float*)(smem + SM_NRM);
    int tid = threadIdx.x;

    // B = pre-split W[r]
    {
        int n = tid >> 2, c = tid & 3;
        const uint4* wr = (const uint4*)(Ws + ((size_t)(r * DIM + n) * 128 + (c & 1) * 32 + (c >> 1) * 64));
        char* db = smem + ((c >> 1) ? SM_BL : SM_BH) + n * 144 + (c & 1) * 64;
#pragma unroll
        for (int j = 0; j < 4; j++) ((uint4*)db)[j] = wr[j];
    }
    // A = gathered pre-split rows (raw; norm applied in epilogue)
    {
        int e = tid >> 1, half = tid & 1;
        char* ah = smem + SM_AH + e * 144 + half * 64;
        char* al = smem + SM_AL + e * 144 + half * 64;
        if (e < m) {
            int sr = g_srcP[s0 + e];
            if (half == 0) { sDst[e] = g_dstP[s0 + e]; sNorm[e] = g_normP[s0 + e]; }
            const uint4* xr = (const uint4*)(Xs + (size_t)sr * 128);
#pragma unroll
            for (int j = 0; j < 4; j++) ((uint4*)ah)[j] = xr[half * 4 + j];
#pragma unroll
            for (int j = 0; j < 4; j++) ((uint4*)al)[j] = xr[8 + half * 4 + j];
        } else {
            uint4 z = make_uint4(0, 0, 0, 0);
#pragma unroll
            for (int j = 0; j < 4; j++) { ((uint4*)ah)[j] = z; ((uint4*)al)[j] = z; }
        }
    }
    __syncthreads();

    int lane = tid & 31, wid = tid >> 5;
    int g = lane >> 2, tg = lane & 3;
    int m0 = wid * 16;

    float c[8][4];
#pragma unroll
    for (int n = 0; n < 8; n++) { c[n][0] = 0.f; c[n][1] = 0.f; c[n][2] = 0.f; c[n][3] = 0.f; }

#pragma unroll
    for (int ks = 0; ks < 4; ks++) {
        int k0 = ks * 16;
        uint32_t ah[4], al[4];
        {
            const char* pLo = smem + SM_AH + ((m0 + g) * SAK + k0 + 2 * tg) * 2;
            const char* pHi = pLo + 8 * SAK * 2;
            ah[0] = *(const uint32_t*)pLo;  ah[1] = *(const uint32_t*)pHi;
            ah[2] = *(const uint32_t*)(pLo + 16); ah[3] = *(const uint32_t*)(pHi + 16);
            const char* qLo = smem + SM_AL + ((m0 + g) * SAK + k0 + 2 * tg) * 2;
            const char* qHi = qLo + 8 * SAK * 2;
            al[0] = *(const uint32_t*)qLo;  al[1] = *(const uint32_t*)qHi;
            al[2] = *(const uint32_t*)(qLo + 16); al[3] = *(const uint32_t*)(qHi + 16);
        }
#pragma unroll
        for (int n = 0; n < 8; n++) {
            uint32_t off = (uint32_t)((n * 8 + g) * SBK + k0 + 2 * tg) * 2;
            uint32_t bh0 = *(const uint32_t*)(smem + SM_BH + off);
            uint32_t bh1 = *(const uint32_t*)(smem + SM_BH + off + 16);
            uint32_t bl0 = *(const uint32_t*)(smem + SM_BL + off);
            uint32_t bl1 = *(const uint32_t*)(smem + SM_BL + off + 16);
            MMA_BF16(c[n], ah, bh0, bh1);
            MMA_BF16(c[n], al, bh0, bh1);
            MMA_BF16(c[n], ah, bl0, bl1);
        }
    }

    // epilogue: apply per-edge norm, shfl-pair, red.global.add.v4
    int  col0 = (tg & 2) * 2;
    bool lead = (tg & 1) == 0;
    int rA = m0 + g, rB = rA + 8;
    int dA = (rA < m) ? sDst[rA] : -1;
    int dB = (rB < m) ? sDst[rB] : -1;
    float nA = (rA < m) ? sNorm[rA] : 0.f;
    float nB = (rB < m) ? sNorm[rB] : 0.f;
#pragma unroll
    for (int n = 0; n < 8; n++) {
        float x0 = c[n][0] * nA, y0 = c[n][1] * nA;
        float x1 = c[n][2] * nB, y1 = c[n][3] * nB;
        float qx0 = __shfl_xor_sync(0xffffffffu, x0, 1);
        float qy0 = __shfl_xor_sync(0xffffffffu, y0, 1);
        float qx1 = __shfl_xor_sync(0xffffffffu, x1, 1);
        float qy1 = __shfl_xor_sync(0xffffffffu, y1, 1);
        if (lead && dA >= 0) {
            float* o = O + (size_t)dA * DIM + n * 8 + col0;
            asm volatile("red.global.add.v4.f32 [%0], {%1,%2,%3,%4};"
                         :: "l"(o), "f"(x0), "f"(y0), "f"(qx0), "f"(qy0) : "memory");
        }
        if (lead && dB >= 0) {
            float* o = O + (size_t)dB * DIM + n * 8 + col0;
            asm volatile("red.global.add.v4.f32 [%0], {%1,%2,%3,%4};"
                         :: "l"(o), "f"(x1), "f"(y1), "f"(qx1), "f"(qy1) : "memory");
        }
    }
}

// ---------------------------------------------------------------- relu (final)
__global__ void k_relu(float* __restrict__ O, int n4) {
    int i = blockIdx.x * blockDim.x + threadIdx.x;
    if (i < n4) {
        float4 v = ((float4*)O)[i];
        v.x = fmaxf(v.x, 0.f); v.y = fmaxf(v.y, 0.f);
        v.z = fmaxf(v.z, 0.f); v.w = fmaxf(v.w, 0.f);
        ((float4*)O)[i] = v;
    }
}

// ---------------------------------------------------------------- launch
extern "C" void kernel_launch(void* const* d_in, const int* in_sizes, int n_in,
                              void* d_out, int out_size) {
    const float* x   = (const float*)d_in[0];
    const int*   src = (const int*)d_in[1];
    const int*   dst = (const int*)d_in[2];
    const int*   et  = (const int*)d_in[3];
    const float* W1  = (const float*)d_in[4];
    const float* Wl1 = (const float*)d_in[5];
    const float* W2  = (const float*)d_in[6];
    const float* Wl2 = (const float*)d_in[7];
    float* out = (float*)d_out;

    void* p;
    cudaGetSymbolAddress(&p, g_h);   float* h  = (float*)p;
    cudaGetSymbolAddress(&p, g_Xs);  __nv_bfloat16* Xs = (__nv_bfloat16*)p;
    cudaGetSymbolAddress(&p, g_Hs);  __nv_bfloat16* Hs = (__nv_bfloat16*)p;
    cudaGetSymbolAddress(&p, g_Ws1); __nv_bfloat16* Ws1 = (__nv_bfloat16*)p;
    cudaGetSymbolAddress(&p, g_Ws2); __nv_bfloat16* Ws2 = (__nv_bfloat16*)p;

    cudaFuncSetAttribute(k_edges,    cudaFuncAttributeMaxDynamicSharedMemorySize, SM_TOT);
    cudaFuncSetAttribute(k_selfloop, cudaFuncAttributeMaxDynamicSharedMemorySize, SM_TOT);

    const int TPB = 256;
    // preprocessing: contention-free counting sort + weight/feature pre-splits
    k_zero<<<(NNODE * NREL / 4 + TPB - 1) / TPB, TPB>>>();
    k_hist<<<NB, TPB>>>(dst, et);
    k_scanRel<<<NREL, 256>>>();
    k_scan<<<1, 128>>>();
    k_tiles<<<(NTILES_MAX + 127) / 128, 128>>>();
    k_scatter<<<NB, TPB>>>(src, dst, et);
    k_wsplit<<<NREL + 1, 256>>>(W1, Wl1, Ws1);
    k_wsplit<<<NREL + 1, 256>>>(W2, Wl2, Ws2);
    k_xsplit<<<(NNODE * 8 + 255) / 256, 256>>>(x, Xs);

    int nBlocksRows = (NNODE + TILE - 1) / TILE;
    int n4 = NNODE * DIM / 4;

    // layer 1: h = relu(edges(x,W1) + x@Wl1)
    k_selfloop<<<nBlocksRows, TPB, SM_TOT>>>(Xs, Ws1, h);
    k_edges<<<NTILES_MAX, TPB, SM_TOT>>>(Xs, Ws1, h);
    k_relu_split<<<(NNODE * 8 + 255) / 256, 256>>>(h, Hs);

    // layer 2: out = relu(edges(h,W2) + h@Wl2)
    k_selfloop<<<nBlocksRows, TPB, SM_TOT>>>(Hs, Ws2, out);
    k_edges<<<NTILES_MAX, TPB, SM_TOT>>>(Hs, Ws2, out);
    k_relu<<<(n4 + TPB - 1) / TPB, TPB>>>(out, n4);
}